// round 3
// baseline (speedup 1.0000x reference)
#include <cuda_runtime.h>
#include <cstdint>
#include <cstddef>

#define Mdim 128
#define Ndim 64
#define Edim 32
#define Sdim 512
#define Bdim 8192

// ---------------- scratch (no allocation allowed) ----------------
__device__ float g_w[Bdim * Edim];   // expert weights: [b*32 + e]

// ---------------- packed f32x2 helpers (sm_103a) ----------------
__device__ __forceinline__ void fma2(unsigned long long& acc, unsigned long long a, unsigned long long b)
{
    asm("fma.rn.f32x2 %0, %1, %2, %3;" : "=l"(acc) : "l"(a), "l"(b), "l"(acc));
}
__device__ __forceinline__ unsigned long long bcast2(float x)
{
    unsigned long long r;
    asm("mov.b64 %0, {%1, %1};" : "=l"(r) : "f"(x));
    return r;
}
__device__ __forceinline__ unsigned long long pack2(float a, float b)
{
    unsigned long long r;
    asm("mov.b64 %0, {%1, %2};" : "=l"(r) : "f"(a), "f"(b));
    return r;
}
__device__ __forceinline__ float2 unpack2(unsigned long long v)
{
    float2 f;
    asm("mov.b64 {%0, %1}, %2;" : "=f"(f.x), "=f"(f.y) : "l"(v));
    return f;
}

// ---------------- Kernel A: fused z_cur + streaming online-softmax attention
// ----------------           + conv-emb + MLP + expert softmax ----------------
#define K2_WARPS 8
#define CHUNK 8

struct OnlineState {
    float mrun, denom, pprev;
    float c0x, c0y, c1x, c1y;
};

__device__ __forceinline__ void row_proc(const float2 v, float zcx, float zcy,
                                         float invT1, OnlineState& st)
{
    float dd = fabsf(v.x - zcx) + fabsf(v.y - zcy);
    dd += __shfl_xor_sync(0xffffffffu, dd, 16);
    dd += __shfl_xor_sync(0xffffffffu, dd, 8);
    dd += __shfl_xor_sync(0xffffffffu, dd, 4);
    dd += __shfl_xor_sync(0xffffffffu, dd, 2);
    dd += __shfl_xor_sync(0xffffffffu, dd, 1);
    float logit = -dd * invT1;
    if (logit > st.mrun) {
        float s = __expf(st.mrun - logit);
        st.denom *= s; st.c0x *= s; st.c0y *= s; st.c1x *= s; st.c1y *= s; st.pprev *= s;
        st.mrun = logit;
    }
    float pw = __expf(logit - st.mrun);
    st.denom += pw;
    st.c0x = fmaf(pw, v.x, st.c0x);       st.c0y = fmaf(pw, v.y, st.c0y);
    st.c1x = fmaf(st.pprev, v.x, st.c1x); st.c1y = fmaf(st.pprev, v.y, st.c1y);
    st.pprev = pw;
}

__device__ __forceinline__ void load_chunk(float2* buf, const float2* p, size_t TSTEP, int cidx)
{
    const float2* q = p + (size_t)cidx * (size_t)CHUNK * TSTEP;
    #pragma unroll
    for (int r = 0; r < CHUNK; ++r) buf[r] = __ldcs(q + (size_t)r * TSTEP);
}

__device__ __forceinline__ void proc_chunk(const float2* buf, float zcx, float zcy,
                                           float invT1, OnlineState& st)
{
    #pragma unroll
    for (int r = 0; r < CHUNK; ++r) row_proc(buf[r], zcx, zcy, invT1, st);
}

__global__ __launch_bounds__(256, 4)
void k_attn(const float* __restrict__ ctx, const float* __restrict__ z,
            const float* __restrict__ noise, const float* __restrict__ Dm,
            const float* __restrict__ sigma_g,
            const float* __restrict__ conv_w, const float* __restrict__ conv_b,
            const float* __restrict__ temp1,
            const float* __restrict__ W1, const float* __restrict__ b1,
            const float* __restrict__ W2, const float* __restrict__ b2,
            const float* __restrict__ temp2)
{
    __shared__ float W1s[192 * 32];          // transposed [j][e]   24 KB
    __shared__ float W2s[32 * 32];           // transposed [j][e]    4 KB
    __shared__ float scomb[K2_WARPS][194];   // per-warp work        6.2 KB
    __shared__ float zs[Mdim][8];            // z[m][bb]             4 KB
    __shared__ float zcs[8][66];             // z_cur[bb][i]         2.1 KB

    int tid = threadIdx.x;
    int b0 = blockIdx.x * K2_WARPS;

    // ---- stage z tile [128 x 8] ----
    #pragma unroll
    for (int r = 0; r < 4; ++r) {
        int idx = tid + r * 256;
        int m = idx >> 3, bb = idx & 7;
        zs[m][bb] = z[(size_t)m * Bdim + b0 + bb];
    }
    // ---- stage MLP weights (transposed) ----
    for (int t = tid; t < 192 * 32; t += 256) {
        int e = t / 192, j = t % 192;
        W1s[j * 32 + e] = W1[t];
    }
    for (int t = tid; t < 32 * 32; t += 256) {
        int e = t / 32, j = t % 32;
        W2s[j * 32 + e] = W2[t];
    }
    __syncthreads();

    // ---- fused z_cur: zc[i][bb] = sigma[i]*noise[i,b] + sum_m D[i,m] z[m,b] ----
    {
        int i = tid >> 2;                    // 0..63
        int bb0 = (tid & 3) * 2;             // 0,2,4,6
        float a0 = sigma_g[i] * noise[(size_t)i * Bdim + b0 + bb0];
        float a1 = sigma_g[i] * noise[(size_t)i * Bdim + b0 + bb0 + 1];
        const float* drow = Dm + i * Mdim;
        #pragma unroll 4
        for (int m = 0; m < Mdim; ++m) {
            float d = __ldg(drow + m);
            float2 zz = *reinterpret_cast<const float2*>(&zs[m][bb0]);
            a0 = fmaf(d, zz.x, a0);
            a1 = fmaf(d, zz.y, a1);
        }
        zcs[bb0][i] = a0;
        zcs[bb0 + 1][i] = a1;
    }
    __syncthreads();

    int warp = tid >> 5, lane = tid & 31;
    int b = b0 + warp;

    float invT1 = 1.0f / fabsf(temp1[0]);
    float invT2 = 1.0f / fabsf(temp2[0]);

    float2 zc2 = *reinterpret_cast<const float2*>(&zcs[warp][2 * lane]);
    float zcx = zc2.x, zcy = zc2.y;

    const float2* p = reinterpret_cast<const float2*>(ctx) + (size_t)b * (Ndim / 2) + lane;
    const size_t TSTEP = (size_t)Bdim * (Ndim / 2);  // float2 per seq step

    OnlineState st;
    st.mrun = -1e30f; st.denom = 0.f; st.pprev = 0.f;
    st.c0x = 0.f; st.c0y = 0.f; st.c1x = 0.f; st.c1y = 0.f;
    float2 buf0[CHUNK], buf1[CHUNK];

    load_chunk(buf0, p, TSTEP, 0);
    for (int cc = 0; cc < 62; cc += 2) {
        load_chunk(buf1, p, TSTEP, cc + 1);
        proc_chunk(buf0, zcx, zcy, invT1, st);
        load_chunk(buf0, p, TSTEP, cc + 2);
        proc_chunk(buf1, zcx, zcy, invT1, st);
    }
    load_chunk(buf1, p, TSTEP, 63);
    proc_chunk(buf0, zcx, zcy, invT1, st);   // chunk 62 (rows 496..503)
    // chunk 63: rows 504..510 normal, row 511 only feeds c1 (shifted tap)
    #pragma unroll
    for (int r = 0; r < CHUNK - 1; ++r) row_proc(buf1[r], zcx, zcy, invT1, st);
    {
        float2 v = buf1[CHUNK - 1];
        st.c1x = fmaf(st.pprev, v.x, st.c1x);
        st.c1y = fmaf(st.pprev, v.y, st.c1y);
    }

    float rinv = 1.0f / st.denom;
    float* sc = scomb[warp];
    sc[2 * lane]      = st.c0x * rinv;  sc[2 * lane + 1]      = st.c0y * rinv;
    sc[64 + 2 * lane] = st.c1x * rinv;  sc[64 + 2 * lane + 1] = st.c1y * rinv;
    __syncwarp();

    // emb[o] = conv_b[o] + sum_i cw0[o,i]*c0[i] + cw1[o,i]*c1[i]
    int o0 = 2 * lane, o1 = 2 * lane + 1;
    float e0 = conv_b[o0], e1 = conv_b[o1];
    const float* cwA = conv_w + (size_t)o0 * 128;   // conv_w[o][i][tap]
    const float* cwB = conv_w + (size_t)o1 * 128;
    #pragma unroll 8
    for (int i = 0; i < 64; ++i) {
        float a = sc[i], c = sc[64 + i];
        e0 = fmaf(__ldg(cwA + 2 * i), a, e0);
        e0 = fmaf(__ldg(cwA + 2 * i + 1), c, e0);
        e1 = fmaf(__ldg(cwB + 2 * i), a, e1);
        e1 = fmaf(__ldg(cwB + 2 * i + 1), c, e1);
    }
    __syncwarp();
    sc[o0] = e0; sc[o1] = e1;                      // combined[0..63] = emb
    #pragma unroll
    for (int k = 0; k < 4; ++k) {
        int j = lane * 4 + k;
        sc[64 + j] = zs[j][warp];                  // combined[64..191] = z[:,b]
    }
    __syncwarp();

    // hidden[e] = relu(W1[e,:] . combined + b1[e]), lane == e
    float hs = b1[lane];
    #pragma unroll 8
    for (int j = 0; j < 192; ++j)
        hs = fmaf(W1s[j * 32 + lane], sc[j], hs);
    hs = fmaxf(hs, 0.f);

    float o2 = b2[lane];
    #pragma unroll
    for (int j = 0; j < 32; ++j)
        o2 = fmaf(W2s[j * 32 + lane], __shfl_sync(0xffffffffu, hs, j), o2);

    // expert softmax over lanes
    float lg = -o2 * invT2;
    float mx = lg;
    mx = fmaxf(mx, __shfl_xor_sync(0xffffffffu, mx, 16));
    mx = fmaxf(mx, __shfl_xor_sync(0xffffffffu, mx, 8));
    mx = fmaxf(mx, __shfl_xor_sync(0xffffffffu, mx, 4));
    mx = fmaxf(mx, __shfl_xor_sync(0xffffffffu, mx, 2));
    mx = fmaxf(mx, __shfl_xor_sync(0xffffffffu, mx, 1));
    float pw2 = __expf(lg - mx);
    float sm2 = pw2;
    sm2 += __shfl_xor_sync(0xffffffffu, sm2, 16);
    sm2 += __shfl_xor_sync(0xffffffffu, sm2, 8);
    sm2 += __shfl_xor_sync(0xffffffffu, sm2, 4);
    sm2 += __shfl_xor_sync(0xffffffffu, sm2, 2);
    sm2 += __shfl_xor_sync(0xffffffffu, sm2, 1);
    g_w[(size_t)b * 32 + lane] = pw2 / sm2;
}

// ---------------- Kernel B: MoE mixture GEMM with packed FFMA2 ----------------
// out[m,b] = sum_{e,k} Wx[e,m,k]*w[e,b]*zcat[k,b] + z[m,b]*(A^T w)[m,b] + (h^T w)[m,b]
#define K3_BT 64
#define K3_MT 64

__global__ __launch_bounds__(256, 2)
void k_mix(const float* __restrict__ z, const float* __restrict__ Wx,
           const float* __restrict__ Amat, const float* __restrict__ hmat,
           float* __restrict__ out)
{
    __shared__ __align__(16) float Ws[2][32][68];   // [stage][k][m]  17.4 KB
    __shared__ __align__(16) float Vs[2][32][66];   // [stage][k][b]  16.9 KB
    __shared__ float w_s[32][65];                   // [e][b]          8.3 KB

    int tid = threadIdx.x;
    int b0 = blockIdx.x * K3_BT;
    int m0 = blockIdx.y * K3_MT;
    int tx = tid & 15, ty = tid >> 4;

    // ---- stage expert-weight tile w_s[e][b] ----
    #pragma unroll
    for (int r = 0; r < 8; ++r) {
        int idx = tid + r * 256;
        int bb = idx >> 5, e = idx & 31;
        w_s[e][bb] = g_w[(size_t)(b0 + bb) * 32 + e];
    }
    __syncthreads();

    // ---- tail terms first (h and A), scalar fp32, reusing smem buffers ----
    #pragma unroll
    for (int r = 0; r < 8; ++r) {
        int idx = tid + r * 256;
        int e = idx >> 6, xx = idx & 63;
        Ws[0][e][xx] = hmat[(size_t)e * Mdim + m0 + xx];
        Ws[1][e][xx] = Amat[(size_t)e * Mdim + m0 + xx];
        Vs[0][e][xx] = w_s[e][xx];
    }
    __syncthreads();

    float hacc[4][4] = {};
    float accA[4][4] = {};
    #pragma unroll
    for (int e = 0; e < 32; ++e) {
        float4 wv = *reinterpret_cast<const float4*>(&Ws[0][e][ty * 4]);
        float4 av = *reinterpret_cast<const float4*>(&Ws[1][e][ty * 4]);
        float2 u0 = *reinterpret_cast<const float2*>(&Vs[0][e][tx * 4]);
        float2 u1 = *reinterpret_cast<const float2*>(&Vs[0][e][tx * 4 + 2]);
        float vv[4] = {u0.x, u0.y, u1.x, u1.y};
        float wvv[4] = {wv.x, wv.y, wv.z, wv.w};
        float avv[4] = {av.x, av.y, av.z, av.w};
        #pragma unroll
        for (int i = 0; i < 4; ++i)
            #pragma unroll
            for (int j = 0; j < 4; ++j) {
                hacc[i][j] = fmaf(wvv[i], vv[j], hacc[i][j]);
                accA[i][j] = fmaf(avv[i], vv[j], accA[i][j]);
            }
    }
    __syncthreads();

    // ---- pack running accumulators into f32x2 pairs ----
    unsigned long long acc[4][2];
    #pragma unroll
    for (int i = 0; i < 4; ++i) {
        acc[i][0] = pack2(hacc[i][0], hacc[i][1]);
        acc[i][1] = pack2(hacc[i][2], hacc[i][3]);
    }

    // ---- main GEMM over 128 (e,k0) chunks, double-buffered ----
    // fill stage: Ws[s][kk][m] = Wx[e, m0+m, k0+kk]; Vs[s][kk][b] = w[e,b]*zcat[k0+kk,b]
    {
        // fill chunk 0
        const float* wxb = Wx + (size_t)0 * (Mdim * Mdim) + (size_t)m0 * Mdim + 0;
        #pragma unroll
        for (int r = 0; r < 2; ++r) {
            int q = tid + r * 256;
            int mm = q >> 3, kq = q & 7;
            float4 v4 = *reinterpret_cast<const float4*>(wxb + (size_t)mm * Mdim + kq * 4);
            Ws[0][kq * 4 + 0][mm] = v4.x;
            Ws[0][kq * 4 + 1][mm] = v4.y;
            Ws[0][kq * 4 + 2][mm] = v4.z;
            Ws[0][kq * 4 + 3][mm] = v4.w;
        }
        #pragma unroll
        for (int r = 0; r < 8; ++r) {
            int idx = tid + r * 256;
            int kk = idx >> 6, bb = idx & 63;
            float zv = z[(size_t)kk * Bdim + b0 + bb];
            Vs[0][kk][bb] = zv * w_s[0][bb];
        }
    }
    __syncthreads();

    for (int c = 0; c < 128; ++c) {
        int s = c & 1;
        if (c < 127) {
            int cn = c + 1;
            int e = cn >> 2, k0 = (cn & 3) << 5;
            int sn = cn & 1;
            const float* wxb = Wx + (size_t)e * (Mdim * Mdim) + (size_t)m0 * Mdim + k0;
            #pragma unroll
            for (int r = 0; r < 2; ++r) {
                int q = tid + r * 256;
                int mm = q >> 3, kq = q & 7;
                float4 v4 = *reinterpret_cast<const float4*>(wxb + (size_t)mm * Mdim + kq * 4);
                Ws[sn][kq * 4 + 0][mm] = v4.x;
                Ws[sn][kq * 4 + 1][mm] = v4.y;
                Ws[sn][kq * 4 + 2][mm] = v4.z;
                Ws[sn][kq * 4 + 3][mm] = v4.w;
            }
            #pragma unroll
            for (int r = 0; r < 8; ++r) {
                int idx = tid + r * 256;
                int kk = idx >> 6, bb = idx & 63;
                int kg = k0 + kk;
                float zv = z[(size_t)kg * Bdim + b0 + bb];
                if (kg >= Mdim - 2) zv = fmaxf(zv, 0.f);   // relu on last P=2 rows
                Vs[sn][kk][bb] = zv * w_s[e][bb];
            }
        }
        // compute on stage s
        #pragma unroll
        for (int kk = 0; kk < 32; ++kk) {
            float4 wv = *reinterpret_cast<const float4*>(&Ws[s][kk][ty * 4]);
            unsigned long long v0 = *reinterpret_cast<const unsigned long long*>(&Vs[s][kk][tx * 4]);
            unsigned long long v1 = *reinterpret_cast<const unsigned long long*>(&Vs[s][kk][tx * 4 + 2]);
            unsigned long long w0 = bcast2(wv.x);
            unsigned long long w1 = bcast2(wv.y);
            unsigned long long w2 = bcast2(wv.z);
            unsigned long long w3 = bcast2(wv.w);
            fma2(acc[0][0], w0, v0); fma2(acc[0][1], w0, v1);
            fma2(acc[1][0], w1, v0); fma2(acc[1][1], w1, v1);
            fma2(acc[2][0], w2, v0); fma2(acc[2][1], w2, v1);
            fma2(acc[3][0], w3, v0); fma2(acc[3][1], w3, v1);
        }
        __syncthreads();
    }

    // ---- epilogue: out = acc + z .* accA ----
    #pragma unroll
    for (int i = 0; i < 4; ++i) {
        int m = m0 + ty * 4 + i;
        float2 r0 = unpack2(acc[i][0]);
        float2 r1 = unpack2(acc[i][1]);
        const float4 zv4 = *reinterpret_cast<const float4*>(z + (size_t)m * Bdim + b0 + tx * 4);
        float4 o4;
        o4.x = r0.x + zv4.x * accA[i][0];
        o4.y = r0.y + zv4.y * accA[i][1];
        o4.z = r1.x + zv4.z * accA[i][2];
        o4.w = r1.y + zv4.w * accA[i][3];
        *reinterpret_cast<float4*>(out + (size_t)m * Bdim + b0 + tx * 4) = o4;
    }
}

// ---------------- launch ----------------
extern "C" void kernel_launch(void* const* d_in, const int* in_sizes, int n_in,
                              void* d_out, int out_size)
{
    const float* z       = (const float*)d_in[0];
    const float* ctx     = (const float*)d_in[1];
    const float* noise   = (const float*)d_in[2];
    const float* conv_w  = (const float*)d_in[3];
    const float* conv_b  = (const float*)d_in[4];
    const float* Dm      = (const float*)d_in[5];
    const float* sigma_g = (const float*)d_in[6];
    const float* temp1   = (const float*)d_in[7];
    const float* W1      = (const float*)d_in[8];
    const float* b1      = (const float*)d_in[9];
    const float* W2      = (const float*)d_in[10];
    const float* b2      = (const float*)d_in[11];
    const float* temp2   = (const float*)d_in[12];
    const float* Amat    = (const float*)d_in[13];
    const float* Wx      = (const float*)d_in[14];
    const float* hmat    = (const float*)d_in[15];
    float* out = (float*)d_out;

    k_attn<<<Bdim / K2_WARPS, 256>>>(ctx, z, noise, Dm, sigma_g,
                                     conv_w, conv_b, temp1, W1, b1, W2, b2, temp2);
    k_mix<<<dim3(Bdim / K3_BT, Mdim / K3_MT), 256>>>(z, Wx, Amat, hmat, out);
}